// round 6
// baseline (speedup 1.0000x reference)
#include <cuda_runtime.h>

// ---------------------------------------------------------------------------
// QHashSoftmax: LUT fixed-point softmax, exact-integer reformulation.
//   idx = clamp(rne(x*16), -128, 127) & 255            (cvt.rni.sat.s8)
//   k[idx] = clip(rint(exp(signed(idx)/16 * scale)*128), 0, 127)   (u8 LUT)
//   S = sum(k) over 1024-element row   (exact integer, < 2^18)
//   t = min(floor(S/k), 1023)   (k=0 -> 1023)  [fp32 div+floor exact here]
//   out = min(rint(128/t), 127) / 128           (t=0 -> inf -> 127)
//
// Structure (R4/R5):
//  - 4 rows / 256-thread block; thread t owns 4 CONSECUTIVE float4s of row
//    t>>6, so every warp lies inside one row -> ONE redux+atomic per warp.
//  - byte-packed codes (pidx/pk u32 per float4), dp4a partial sums (unsigned).
//  - exp table u8[256] = 64 smem words (gather conflict deg <= 2);
//    out table by k: u8[128] = 32 words, one/bank -> conflict-FREE gather.
//  - __launch_bounds__(256,6) caps regs so the R3 occupancy cliff can't recur.
// ---------------------------------------------------------------------------

__device__ unsigned char g_exp_u8[256];   // indexed by wrapped code (q & 255)

__global__ void qhs_setup_kernel(const float* __restrict__ scale_ptr) {
    int i = threadIdx.x;                      // 0..255 = wrapped address
    float scale = *scale_ptr;
    int sv = (i >= 128) ? (i - 256) : i;      // two's-complement decode
    float val = (float)sv * 0.0625f * scale;  // fp32, matches reference
    double e = exp((double)val);              // high-precision exp
    double r = rint(e * 128.0);               // round half to even
    if (r > 127.0) r = 127.0;
    if (r < 0.0)   r = 0.0;
    g_exp_u8[i] = (unsigned char)(int)r;
}

// clamp(round-half-even(f), -128, 127) & 255 in one convert + one mask
__device__ __forceinline__ unsigned qhs_code(float f) {
    int r;
    asm("cvt.rni.sat.s8.f32 %0, %1;" : "=r"(r) : "f"(f));
    return (unsigned)r & 255u;
}

#define ROWS_PER_BLOCK 4

__global__ __launch_bounds__(256, 6) void qhs_main_kernel(
    const float4* __restrict__ x, float4* __restrict__ out)
{
    __shared__ unsigned char sk8[256];                    // exp codes (u8)
    __shared__ unsigned char ocode[ROWS_PER_BLOCK][128];  // out codes by k
    __shared__ int sS[ROWS_PER_BLOCK];                    // row sums

    const int tid = threadIdx.x;
    const int row = tid >> 6;          // 4 rows, 64 threads each
    const int c   = tid & 63;          // position within row (x4 float4)

    sk8[tid] = g_exp_u8[tid];
    if (tid < ROWS_PER_BLOCK) sS[tid] = 0;

    // Thread's 4 consecutive float4s of its row (warp = 2KB contiguous).
    const long long tbase =
        (long long)blockIdx.x * (ROWS_PER_BLOCK * 256) + row * 256 + c * 4;

    float4 v0 = __ldcs(&x[tbase + 0]);
    float4 v1 = __ldcs(&x[tbase + 1]);
    float4 v2 = __ldcs(&x[tbase + 2]);
    float4 v3 = __ldcs(&x[tbase + 3]);

    // Quantize to packed 8-bit codes (independent of tables).
    unsigned pidx[4];
#define QHS_PACK(j, v)                                                  \
    pidx[j] = qhs_code(v.x * 16.0f)          |                          \
              (qhs_code(v.y * 16.0f) << 8)   |                          \
              (qhs_code(v.z * 16.0f) << 16)  |                          \
              (qhs_code(v.w * 16.0f) << 24)
    QHS_PACK(0, v0); QHS_PACK(1, v1); QHS_PACK(2, v2); QHS_PACK(3, v3);
#undef QHS_PACK

    __syncthreads();   // sk8 + sS ready

    // ---- Phase 1: gather k bytes, pack, one redux+atomic per warp -------
    unsigned pk[4];
    unsigned s = 0u;
#pragma unroll
    for (int j = 0; j < 4; j++) {
        unsigned p = pidx[j];
        unsigned k0 = sk8[p & 255u];
        unsigned k1 = sk8[(p >> 8) & 255u];
        unsigned k2 = sk8[(p >> 16) & 255u];
        unsigned k3 = sk8[p >> 24];
        pk[j] = k0 | (k1 << 8) | (k2 << 16) | (k3 << 24);
        s = __dp4a(pk[j], 0x01010101u, s);
    }
    int si = __reduce_add_sync(0xFFFFFFFFu, (int)s);  // warp fully in one row
    if ((tid & 31) == 0) atomicAdd(&sS[row], si);

    __syncthreads();   // all sums complete

    // ---- Phase 2: per-row output-code tables (indexed by k) -------------
    // 4 rows x 128 entries = 512; each thread builds 2.
#pragma unroll
    for (int e = tid; e < ROWS_PER_BLOCK * 128; e += 256) {
        int rw = e >> 7;
        int kk = e & 127;
        float Sf = (float)sS[rw];                      // exact (< 2^18)
        // floor(S/k): IEEE div then floor — exact (err 0.0078/k < 1/k gap).
        // kk==0 -> +inf -> clipped to 1023 (reference e==0 branch).
        float t = fminf(floorf(__fdiv_rn(Sf, (float)kk)), 1023.0f);
        // t==0 -> +inf -> clipped to 127 (reference 1/0 saturation).
        float code = fminf(rintf(__fdiv_rn(128.0f, t)), 127.0f);
        ocode[rw][kk] = (unsigned char)(int)code;
    }

    __syncthreads();   // tables ready

    // ---- Phase 3: conflict-free byte gathers + streaming stores ---------
#pragma unroll
    for (int j = 0; j < 4; j++) {
        unsigned p = pk[j];
        float4 o;
        o.x = (float)ocode[row][p & 255u]         * 0.0078125f;
        o.y = (float)ocode[row][(p >> 8) & 255u]  * 0.0078125f;
        o.z = (float)ocode[row][(p >> 16) & 255u] * 0.0078125f;
        o.w = (float)ocode[row][p >> 24]          * 0.0078125f;
        __stcs(&out[tbase + j], o);
    }
}

extern "C" void kernel_launch(void* const* d_in, const int* in_sizes, int n_in,
                              void* d_out, int out_size) {
    const float* x     = (const float*)d_in[0];   // [4,12,1024,1024] fp32
    const float* scale = (const float*)d_in[1];   // scalar fp32

    const int n_elems = in_sizes[0];
    const int n_rows  = n_elems >> 10;                   // rows of 1024
    const int n_blocks = n_rows / ROWS_PER_BLOCK;

    qhs_setup_kernel<<<1, 256>>>(scale);
    qhs_main_kernel<<<n_blocks, 256>>>((const float4*)x, (float4*)d_out);
}

// round 7
// speedup vs baseline: 1.4361x; 1.4361x over previous
#include <cuda_runtime.h>

// ---------------------------------------------------------------------------
// QHashSoftmax: LUT fixed-point softmax, exact-integer reformulation.
//   idx = clamp(rne(x*16), -128, 127) & 255            (cvt.rni.sat.s8)
//   k[idx] = clip(rint(exp(signed(idx)/16 * scale)*128), 0, 127)   (u8 LUT)
//   S = sum(k) over 1024-element row   (exact integer, < 2^18)
//   t = min(floor(S/k), 1023)   (k=0 -> 1023)  [fp32 div+floor exact here]
//   out = min(rint(128/t), 127) / 128           (t=0 -> inf -> 127)
//
// Structure (R6 = R2 layout + R5 ALU):
//  - 4 rows / 256-thread block, thread t handles float4 index t of EACH row
//    (rows at +256): every LDG/STG is per-instruction fully coalesced.
//  - byte-packed codes (pidx/pk u32), dp4a partial sums.
//  - packed-pair redux: rows (0,1) and (2,3) share one u32 (16-bit halves,
//    32-lane partial sums <= 16256 < 2^15, no carry) -> 2 REDUX per thread.
//  - exp table u8[256] = 64 smem words (gather conflict deg <= 2);
//    out table by k: u8[128] = 32 words, one/bank -> conflict-FREE gather.
//  - __launch_bounds__(256,6) occupancy guard; .cs streaming hints.
// ---------------------------------------------------------------------------

__device__ unsigned char g_exp_u8[256];   // indexed by wrapped code (q & 255)

__global__ void qhs_setup_kernel(const float* __restrict__ scale_ptr) {
    int i = threadIdx.x;                      // 0..255 = wrapped address
    float scale = *scale_ptr;
    int sv = (i >= 128) ? (i - 256) : i;      // two's-complement decode
    float val = (float)sv * 0.0625f * scale;  // fp32, matches reference
    double e = exp((double)val);              // high-precision exp
    double r = rint(e * 128.0);               // round half to even
    if (r > 127.0) r = 127.0;
    if (r < 0.0)   r = 0.0;
    g_exp_u8[i] = (unsigned char)(int)r;
}

// clamp(round-half-even(f), -128, 127) & 255 in one convert + one mask
__device__ __forceinline__ unsigned qhs_code(float f) {
    int r;
    asm("cvt.rni.sat.s8.f32 %0, %1;" : "=r"(r) : "f"(f));
    return (unsigned)r & 255u;
}

#define ROWS_PER_BLOCK 4

__global__ __launch_bounds__(256, 6) void qhs_main_kernel(
    const float4* __restrict__ x, float4* __restrict__ out)
{
    __shared__ unsigned char sk8[256];                    // exp codes (u8)
    __shared__ unsigned char ocode[ROWS_PER_BLOCK][128];  // out codes by k
    __shared__ int sS[ROWS_PER_BLOCK];                    // row sums

    const int tid = threadIdx.x;

    sk8[tid] = g_exp_u8[tid];
    if (tid < ROWS_PER_BLOCK) sS[tid] = 0;

    // Coalesced: thread t -> float4 index t of each of the block's 4 rows.
    const long long base =
        (long long)blockIdx.x * (ROWS_PER_BLOCK * 256) + tid;

    float4 v0 = __ldcs(&x[base]);
    float4 v1 = __ldcs(&x[base + 256]);
    float4 v2 = __ldcs(&x[base + 512]);
    float4 v3 = __ldcs(&x[base + 768]);

    // Quantize to packed 8-bit codes (independent of tables).
    unsigned pidx[4];
#define QHS_PACK(j, v)                                                  \
    pidx[j] = qhs_code(v.x * 16.0f)          |                          \
              (qhs_code(v.y * 16.0f) << 8)   |                          \
              (qhs_code(v.z * 16.0f) << 16)  |                          \
              (qhs_code(v.w * 16.0f) << 24)
    QHS_PACK(0, v0); QHS_PACK(1, v1); QHS_PACK(2, v2); QHS_PACK(3, v3);
#undef QHS_PACK

    __syncthreads();   // sk8 + sS ready

    // ---- Phase 1: gather k bytes, pack, packed-pair redux ---------------
    unsigned pk[4];
    unsigned d[4];
#pragma unroll
    for (int j = 0; j < 4; j++) {
        unsigned p = pidx[j];
        unsigned k0 = sk8[p & 255u];
        unsigned k1 = sk8[(p >> 8) & 255u];
        unsigned k2 = sk8[(p >> 16) & 255u];
        unsigned k3 = sk8[p >> 24];
        pk[j] = k0 | (k1 << 8) | (k2 << 16) | (k3 << 24);
        d[j] = __dp4a(pk[j], 0x01010101u, 0u);     // <= 508
    }
    // rows (0,1) and (2,3) in 16-bit halves; 32-lane sum <= 16256 (no carry)
    unsigned s01 = __reduce_add_sync(0xFFFFFFFFu, d[0] | (d[1] << 16));
    unsigned s23 = __reduce_add_sync(0xFFFFFFFFu, d[2] | (d[3] << 16));
    if ((tid & 31) == 0) {
        atomicAdd(&sS[0], (int)(s01 & 0xFFFFu));
        atomicAdd(&sS[1], (int)(s01 >> 16));
        atomicAdd(&sS[2], (int)(s23 & 0xFFFFu));
        atomicAdd(&sS[3], (int)(s23 >> 16));
    }

    __syncthreads();   // all sums complete

    // ---- Phase 2: per-row output-code tables (indexed by k) -------------
    // 4 rows x 128 entries = 512; each thread builds 2.
#pragma unroll
    for (int e = tid; e < ROWS_PER_BLOCK * 128; e += 256) {
        int rw = e >> 7;
        int kk = e & 127;
        float Sf = (float)sS[rw];                      // exact (< 2^18)
        // floor(S/k): IEEE div then floor — exact (err 0.0078/k < 1/k gap).
        // kk==0 -> +inf -> clipped to 1023 (reference e==0 branch).
        float t = fminf(floorf(__fdiv_rn(Sf, (float)kk)), 1023.0f);
        // t==0 -> +inf -> clipped to 127 (reference 1/0 saturation).
        float code = fminf(rintf(__fdiv_rn(128.0f, t)), 127.0f);
        ocode[rw][kk] = (unsigned char)(int)code;
    }

    __syncthreads();   // tables ready

    // ---- Phase 3: conflict-free byte gathers + coalesced stores ---------
#pragma unroll
    for (int j = 0; j < 4; j++) {
        unsigned p = pk[j];
        float4 o;
        o.x = (float)ocode[j][p & 255u]         * 0.0078125f;
        o.y = (float)ocode[j][(p >> 8) & 255u]  * 0.0078125f;
        o.z = (float)ocode[j][(p >> 16) & 255u] * 0.0078125f;
        o.w = (float)ocode[j][p >> 24]          * 0.0078125f;
        __stcs(&out[base + j * 256], o);
    }
}

extern "C" void kernel_launch(void* const* d_in, const int* in_sizes, int n_in,
                              void* d_out, int out_size) {
    const float* x     = (const float*)d_in[0];   // [4,12,1024,1024] fp32
    const float* scale = (const float*)d_in[1];   // scalar fp32

    const int n_elems = in_sizes[0];
    const int n_rows  = n_elems >> 10;                   // rows of 1024
    const int n_blocks = n_rows / ROWS_PER_BLOCK;

    qhs_setup_kernel<<<1, 256>>>(scale);
    qhs_main_kernel<<<n_blocks, 256>>>((const float4*)x, (float4*)d_out);
}